// round 3
// baseline (speedup 1.0000x reference)
#include <cuda_runtime.h>

// Shapes (fixed by the problem)
#define NB   8
#define CIN  256
#define COUT 256
#define LL   1024
#define VV   25
#define PP   3
#define KWIN 9
#define SPAD 26   // padded s row (104B, 8B aligned for float2)

// Scratch (device globals: allocation-free rule)
__device__ float g_s[NB * CIN * LL * VV];          // temporal sliding sums, 210MB
__device__ float g_Wt[CIN * PP * COUT];            // Wt[ci][o], o = p*256+c (row len 768)
__device__ float g_Aeff[PP * VV * VV];             // A_p * edge_importance

// ---------------------------------------------------------------------------
// K0: prep — transpose conv_w into Wt[ci][o]; fold edge_importance into A.
// grid <<<768, 256>>> ; block b = o, thread t = ci
// ---------------------------------------------------------------------------
__global__ void prep_kernel(const float* __restrict__ conv_w,
                            const float* __restrict__ A1,
                            const float* __restrict__ A2,
                            const float* __restrict__ A3,
                            const float* __restrict__ ei) {
    int o  = blockIdx.x;     // 0..767
    int ci = threadIdx.x;    // 0..255
    g_Wt[ci * (PP * COUT) + o] = conv_w[o * CIN + ci];

    int i = blockIdx.x * 256 + threadIdx.x;
    if (i < PP * VV * VV) {
        int p = i / (VV * VV);
        int r = i % (VV * VV);
        const float* Ap = (p == 0) ? A1 : ((p == 1) ? A2 : A3);
        g_Aeff[i] = Ap[r] * ei[i];   // ei is (P, V*V) flat
    }
}

// ---------------------------------------------------------------------------
// K1: temporal causal 9-tap sliding sum over L:
//     s[n,ci,m,v] = sum_{l=max(0,m-8)}^{m} x[n,ci,l,v]
// one thread per (n, ci, v); running sum (add new, subtract 9-old).
// ---------------------------------------------------------------------------
__global__ void temporal_kernel(const float* __restrict__ x) {
    int t = blockIdx.x * blockDim.x + threadIdx.x;
    if (t >= NB * CIN * VV) return;
    int v  = t % VV;
    int rc = t / VV;                         // n*CIN + ci
    int base = rc * (LL * VV) + v;

    float run = 0.f;
    #pragma unroll 4
    for (int m = 0; m < LL; ++m) {
        run += x[base + m * VV];
        if (m >= KWIN) run -= x[base + (m - KWIN) * VV];
        g_s[base + m * VV] = run;
    }
}

// ---------------------------------------------------------------------------
// K2: per-(n,m) fused block:
//   Y[o,v]   = sum_ci Wt[ci][o] * s[n,ci,m,v]           (GEMM 768x256x25)
//   Y[o,v]  += n_l(m) * b[o]
//   out[c,w] = sum_p sum_v Y[p*256+c, v] * Aeff[p][v][w]
//   LayerNorm over (c,w), affine, relu, +residual x, relu, store.
// 256 threads: thread t owns c = t (rows t, t+256, t+512 of Y).
// ---------------------------------------------------------------------------
__global__ __launch_bounds__(256, 2)
void main_kernel(const float* __restrict__ x,
                 const float* __restrict__ conv_b,
                 const float* __restrict__ ln_gamma,
                 const float* __restrict__ ln_beta,
                 float* __restrict__ out) {
    __shared__ float s_sh[CIN * SPAD];       // 26.6 KB
    __shared__ float a_sh[PP * VV * VV];     // 7.5 KB
    __shared__ float red[16];                // 8 warp sums + 8 warp sumsq

    const int n = blockIdx.x >> 10;
    const int m = blockIdx.x & 1023;
    const int t = threadIdx.x;

    // load s slice: s[n, t, m, 0..24]
    {
        const int sbase = ((n * CIN + t) * LL + m) * VV;
        #pragma unroll
        for (int v = 0; v < VV; ++v) s_sh[t * SPAD + v] = g_s[sbase + v];
    }
    for (int i = t; i < PP * VV * VV; i += 256) a_sh[i] = g_Aeff[i];
    __syncthreads();

    float acc0[VV], acc1[VV], acc2[VV];
    #pragma unroll
    for (int v = 0; v < VV; ++v) { acc0[v] = 0.f; acc1[v] = 0.f; acc2[v] = 0.f; }

    // main GEMM: K = 256 channels
    #pragma unroll 4
    for (int k = 0; k < CIN; ++k) {
        const float w0 = g_Wt[k * 768 + t];
        const float w1 = g_Wt[k * 768 + t + 256];
        const float w2 = g_Wt[k * 768 + t + 512];
        const float* sr = &s_sh[k * SPAD];
        #pragma unroll
        for (int j = 0; j < 12; ++j) {
            const float2 sv = *(const float2*)(sr + 2 * j);
            acc0[2*j]   = fmaf(w0, sv.x, acc0[2*j]);
            acc1[2*j]   = fmaf(w1, sv.x, acc1[2*j]);
            acc2[2*j]   = fmaf(w2, sv.x, acc2[2*j]);
            acc0[2*j+1] = fmaf(w0, sv.y, acc0[2*j+1]);
            acc1[2*j+1] = fmaf(w1, sv.y, acc1[2*j+1]);
            acc2[2*j+1] = fmaf(w2, sv.y, acc2[2*j+1]);
        }
        const float svl = sr[24];
        acc0[24] = fmaf(w0, svl, acc0[24]);
        acc1[24] = fmaf(w1, svl, acc1[24]);
        acc2[24] = fmaf(w2, svl, acc2[24]);
    }

    // bias: y had +b[o] per l; after temporal sum that's n_l(m) * b[o]
    {
        const float nl = (float)((m + 1 < KWIN) ? (m + 1) : KWIN);
        const float b0 = nl * conv_b[t];
        const float b1 = nl * conv_b[t + 256];
        const float b2 = nl * conv_b[t + 512];
        #pragma unroll
        for (int v = 0; v < VV; ++v) { acc0[v] += b0; acc1[v] += b1; acc2[v] += b2; }
    }

    // spatial epilogue: out[c,w] = sum_p sum_v Y_p[v] * Aeff[p][v][w]
    float ov[VV];
    #pragma unroll
    for (int w = 0; w < VV; ++w) ov[w] = 0.f;
    #pragma unroll
    for (int v = 0; v < VV; ++v) {
        const float a0 = acc0[v], a1 = acc1[v], a2 = acc2[v];
        const float* Ar0 = &a_sh[(0 * VV + v) * VV];
        const float* Ar1 = &a_sh[(1 * VV + v) * VV];
        const float* Ar2 = &a_sh[(2 * VV + v) * VV];
        #pragma unroll
        for (int w = 0; w < VV; ++w) {
            float o0 = fmaf(a0, Ar0[w], ov[w]);
            o0 = fmaf(a1, Ar1[w], o0);
            ov[w] = fmaf(a2, Ar2[w], o0);
        }
    }

    // LayerNorm over (c=256, w=25) = 6400 elements
    float sm = 0.f, sq = 0.f;
    #pragma unroll
    for (int w = 0; w < VV; ++w) { sm += ov[w]; sq = fmaf(ov[w], ov[w], sq); }
    #pragma unroll
    for (int off = 16; off > 0; off >>= 1) {
        sm += __shfl_xor_sync(0xFFFFFFFFu, sm, off);
        sq += __shfl_xor_sync(0xFFFFFFFFu, sq, off);
    }
    const int warp = t >> 5;
    if ((t & 31) == 0) { red[warp] = sm; red[8 + warp] = sq; }
    __syncthreads();
    float tsum = 0.f, tsq = 0.f;
    #pragma unroll
    for (int i = 0; i < 8; ++i) { tsum += red[i]; tsq += red[8 + i]; }
    const float mean = tsum * (1.f / 6400.f);
    const float var  = tsq * (1.f / 6400.f) - mean * mean;
    const float rstd = rsqrtf(var + 1e-5f);

    // affine + relu + residual + relu + store
    const int xb = ((n * CIN + t) * LL + m) * VV;
    #pragma unroll
    for (int w = 0; w < VV; ++w) {
        const float g  = ln_gamma[t * VV + w];
        const float be = ln_beta[t * VV + w];
        float h = fmaf((ov[w] - mean) * rstd, g, be);
        h = fmaxf(h, 0.f);
        const float r = x[xb + w];
        out[xb + w] = fmaxf(h + r, 0.f);
    }
}

// ---------------------------------------------------------------------------
extern "C" void kernel_launch(void* const* d_in, const int* in_sizes, int n_in,
                              void* d_out, int out_size) {
    const float* x      = (const float*)d_in[0];
    const float* A1     = (const float*)d_in[1];
    const float* A2     = (const float*)d_in[2];
    const float* A3     = (const float*)d_in[3];
    const float* conv_w = (const float*)d_in[4];
    const float* conv_b = (const float*)d_in[5];
    const float* gamma  = (const float*)d_in[6];
    const float* beta   = (const float*)d_in[7];
    const float* ei     = (const float*)d_in[8];
    float* out          = (float*)d_out;

    prep_kernel<<<PP * COUT, CIN>>>(conv_w, A1, A2, A3, ei);
    temporal_kernel<<<(NB * CIN * VV + 255) / 256, 256>>>(x);
    main_kernel<<<NB * LL, 256>>>(x, conv_b, gamma, beta, out);
}